// round 10
// baseline (speedup 1.0000x reference)
#include <cuda_runtime.h>
#include <cuda_bf16.h>
#include <cstdint>

#define NT 8192      // tokens
#define DIM 1024     // model dim

// ---------------- static device scratch (no allocs allowed) ----------------
__device__ float d_qhat[(size_t)NT * DIM];
__device__ float d_khat[(size_t)NT * DIM];
__device__ float d_g   [(size_t)NT * DIM];
__device__ float d_S   [(size_t)NT * NT];            // scores fp32 (256 MB)
__device__ __nv_bfloat16 d_Sh[(size_t)NT * NT];      // attn hi (128 MB)
__device__ __nv_bfloat16 d_Sl[(size_t)NT * NT];      // attn lo (128 MB)
__device__ __nv_bfloat16 d_xh[(size_t)NT * DIM];
__device__ __nv_bfloat16 d_xl[(size_t)NT * DIM];
__device__ __nv_bfloat16 d_qch[(size_t)NT * DIM];
__device__ __nv_bfloat16 d_qcl[(size_t)NT * DIM];
__device__ __nv_bfloat16 d_kch[(size_t)NT * DIM];
__device__ __nv_bfloat16 d_kcl[(size_t)NT * DIM];
__device__ __nv_bfloat16 d_gTh[(size_t)DIM * NT];
__device__ __nv_bfloat16 d_gTl[(size_t)DIM * NT];
__device__ __nv_bfloat16 d_WTh[(size_t)3 * DIM * DIM];
__device__ __nv_bfloat16 d_WTl[(size_t)3 * DIM * DIM];
__device__ float d_part[3 * 32 * DIM];
__device__ float d_colred[3 * DIM];                  // [mq | mk | gsum]
__device__ float d_m[NT];
__device__ float d_gate[NT];

// ---------------- small helpers ----------------
__device__ __forceinline__ float warpMax(float v) {
    #pragma unroll
    for (int o = 16; o > 0; o >>= 1) v = fmaxf(v, __shfl_xor_sync(0xffffffffu, v, o));
    return v;
}
__device__ __forceinline__ float warpSum(float v) {
    #pragma unroll
    for (int o = 16; o > 0; o >>= 1) v += __shfl_xor_sync(0xffffffffu, v, o);
    return v;
}
__device__ __forceinline__ uint32_t smem_u32(const void* p) {
    uint32_t a;
    asm("{ .reg .u64 t; cvta.to.shared.u64 t, %1; cvt.u32.u64 %0, t; }" : "=r"(a) : "l"(p));
    return a;
}
__device__ __forceinline__ void f2split(float v, __nv_bfloat16& h, __nv_bfloat16& l) {
    h = __float2bfloat16_rn(v);
    l = __float2bfloat16_rn(v - __bfloat162float(h));
}

// ---------------- mma.sync / ldmatrix / cp.async wrappers (base ISA) ----------------
__device__ __forceinline__ void ldsm_x4(uint32_t& r0, uint32_t& r1, uint32_t& r2, uint32_t& r3,
                                        uint32_t addr) {
    asm volatile("ldmatrix.sync.aligned.m8n8.x4.shared.b16 {%0,%1,%2,%3}, [%4];"
                 : "=r"(r0), "=r"(r1), "=r"(r2), "=r"(r3) : "r"(addr));
}
__device__ __forceinline__ void mma_bf16(float* c, const uint32_t* a, const uint32_t* b) {
    asm volatile("mma.sync.aligned.m16n8k16.row.col.f32.bf16.bf16.f32 "
                 "{%0,%1,%2,%3}, {%4,%5,%6,%7}, {%8,%9}, {%0,%1,%2,%3};"
                 : "+f"(c[0]), "+f"(c[1]), "+f"(c[2]), "+f"(c[3])
                 : "r"(a[0]), "r"(a[1]), "r"(a[2]), "r"(a[3]), "r"(b[0]), "r"(b[1]));
}
__device__ __forceinline__ void cp16(uint32_t dst, const void* src) {
    asm volatile("cp.async.cg.shared.global [%0], [%1], 16;" :: "r"(dst), "l"(src));
}
__device__ __forceinline__ void cp_commit() {
    asm volatile("cp.async.commit_group;" ::: "memory");
}
__device__ __forceinline__ void cp_wait1() {
    asm volatile("cp.async.wait_group 1;" ::: "memory");
}

// smem tile: 128 rows x 64 bf16 (128B/row); 16B unit c in 0..7, u = c ^ (row&7)
__device__ __forceinline__ uint32_t sw_addr(uint32_t base, int row, int c) {
    return base + (uint32_t)(row * 128) + (uint32_t)((c ^ (row & 7)) << 4);
}

// ---------------- pipelined split-bf16 mma.sync GEMM ----------------
// C[M,N] = (Ah+Al)[M,K] @ (Bh+Bl)^T, B stored [N,K] row-major, bf16 hi/lo operands.
// 128x128 block, BK=64, 512 threads (16 warps, 4x4), warp tile 32x32, 3-stage cp.async.
// CTA raster: 8-wide column bands (rows fastest) for L2 operand reuse.
static constexpr int STAGE_BYTES = 65536;            // Ah|Al|Bh|Bl each 16 KB
static constexpr int GEMM_STAGES = 3;
static constexpr int GEMM_SMEM   = GEMM_STAGES * STAGE_BYTES;  // 192 KB

template <bool EPI>
__global__ __launch_bounds__(512, 1)
void mmagemm(const __nv_bfloat16* __restrict__ Ah, const __nv_bfloat16* __restrict__ Al,
             const __nv_bfloat16* __restrict__ Bh, const __nv_bfloat16* __restrict__ Bl,
             float* __restrict__ C, int K,
             const float* __restrict__ gate, const float* __restrict__ gsum,
             const float* __restrict__ xres)
{
    extern __shared__ char smem[];
    const uint32_t su = smem_u32(smem);
    const int tid  = threadIdx.x;
    const int wid  = tid >> 5, lane = tid & 31;
    const int warpM = wid >> 2, warpN = wid & 3;     // 4 x 4 warps, warp tile 32x32

    // CTA raster swizzle: 8-wide column bands, rows fastest within a band
    const int bid  = blockIdx.y * gridDim.x + blockIdx.x;
    const int grp  = bid / (8 * gridDim.y);
    const int rem  = bid - grp * (8 * gridDim.y);
    const int rowBase = (rem >> 3) * 128;
    const int colBase = (grp * 8 + (rem & 7)) * 128;
    const int ldcN = gridDim.x * 128;

    // loader: 512 threads; each does 2x16B per matrix per stage (rows lr and lr+64)
    const int lr = tid >> 3, lc = tid & 7;           // row 0..63, unit 0..7
    const __nv_bfloat16* gAh = Ah + (size_t)(rowBase + lr) * K + lc * 8;
    const __nv_bfloat16* gAl = Al + (size_t)(rowBase + lr) * K + lc * 8;
    const __nv_bfloat16* gBh = Bh + (size_t)(colBase + lr) * K + lc * 8;
    const __nv_bfloat16* gBl = Bl + (size_t)(colBase + lr) * K + lc * 8;
    const size_t rstep = (size_t)64 * K;

    const int KIT = K >> 6;

    auto issue = [&](int stage) {
        const uint32_t sb = su + (uint32_t)(stage % 3) * STAGE_BYTES;
        const int k0 = stage << 6;
        cp16(sw_addr(sb,          lr,      lc), gAh + k0);
        cp16(sw_addr(sb,          lr + 64, lc), gAh + rstep + k0);
        cp16(sw_addr(sb + 16384u, lr,      lc), gAl + k0);
        cp16(sw_addr(sb + 16384u, lr + 64, lc), gAl + rstep + k0);
        cp16(sw_addr(sb + 32768u, lr,      lc), gBh + k0);
        cp16(sw_addr(sb + 32768u, lr + 64, lc), gBh + rstep + k0);
        cp16(sw_addr(sb + 49152u, lr,      lc), gBl + k0);
        cp16(sw_addr(sb + 49152u, lr + 64, lc), gBl + rstep + k0);
    };

    // prologue: stages 0..1
    issue(0); cp_commit();
    if (KIT > 1) issue(1);
    cp_commit();

    float acc[2][4][4];
    #pragma unroll
    for (int i = 0; i < 2; i++)
        #pragma unroll
        for (int j = 0; j < 4; j++)
            #pragma unroll
            for (int k = 0; k < 4; k++) acc[i][j][k] = 0.0f;

    // ldmatrix lane addressing
    const int aRow = warpM * 32 + (lane & 15);       // + tm*16
    const int aC   = lane >> 4;                      // 0/1
    const int bRow = warpN * 32 + (lane & 7) + ((lane >> 4) << 3);  // + pair*16
    const int bC   = (lane >> 3) & 1;                // 0/1

    for (int it = 0; it < KIT; ++it) {
        cp_wait1();
        __syncthreads();
        if (it + 2 < KIT) issue(it + 2);
        cp_commit();                                  // empty commit keeps count uniform

        const uint32_t sb = su + (uint32_t)(it % 3) * STAGE_BYTES;
        #pragma unroll
        for (int kh = 0; kh < 4; kh++) {
            uint32_t ah[2][4], al[2][4], bfh[4][2], bfl[4][2];
            #pragma unroll
            for (int tm = 0; tm < 2; tm++) {
                ldsm_x4(ah[tm][0], ah[tm][1], ah[tm][2], ah[tm][3],
                        sw_addr(sb, aRow + tm * 16, kh * 2 + aC));
                ldsm_x4(al[tm][0], al[tm][1], al[tm][2], al[tm][3],
                        sw_addr(sb + 16384u, aRow + tm * 16, kh * 2 + aC));
            }
            #pragma unroll
            for (int p = 0; p < 2; p++) {            // n-tile pairs (2p, 2p+1)
                ldsm_x4(bfh[2*p][0], bfh[2*p][1], bfh[2*p+1][0], bfh[2*p+1][1],
                        sw_addr(sb + 32768u, bRow + p * 16, kh * 2 + bC));
                ldsm_x4(bfl[2*p][0], bfl[2*p][1], bfl[2*p+1][0], bfl[2*p+1][1],
                        sw_addr(sb + 49152u, bRow + p * 16, kh * 2 + bC));
            }
            #pragma unroll
            for (int tm = 0; tm < 2; tm++)
                #pragma unroll
                for (int tn = 0; tn < 4; tn++) {
                    mma_bf16(acc[tm][tn], ah[tm], bfh[tn]);
                    mma_bf16(acc[tm][tn], ah[tm], bfl[tn]);
                    mma_bf16(acc[tm][tn], al[tm], bfh[tn]);
                }
        }
    }

    // epilogue: direct stores
    const int g  = lane >> 2;
    const int t4 = lane & 3;
    #pragma unroll
    for (int tm = 0; tm < 2; tm++) {
        const int row = rowBase + warpM * 32 + tm * 16 + g;
        #pragma unroll
        for (int tn = 0; tn < 4; tn++) {
            const int col = colBase + warpN * 32 + tn * 8 + t4 * 2;
            float v0 = acc[tm][tn][0], v1 = acc[tm][tn][1];
            float v2 = acc[tm][tn][2], v3 = acc[tm][tn][3];
            if (EPI) {
                const float gt0 = gate[row], gt8 = gate[row + 8];
                const float2 gs = *reinterpret_cast<const float2*>(gsum + col);
                const float2 x0 = *reinterpret_cast<const float2*>(
                    xres + (size_t)row * ldcN + col);
                const float2 x8 = *reinterpret_cast<const float2*>(
                    xres + (size_t)(row + 8) * ldcN + col);
                v0 += gt0 * gs.x + x0.x;  v1 += gt0 * gs.y + x0.y;
                v2 += gt8 * gs.x + x8.x;  v3 += gt8 * gs.y + x8.y;
            }
            *reinterpret_cast<float2*>(C + (size_t)row * ldcN + col) = make_float2(v0, v1);
            *reinterpret_cast<float2*>(C + (size_t)(row + 8) * ldcN + col) = make_float2(v2, v3);
        }
    }
}

// ---------------- elementwise split: fp32 -> bf16 hi/lo ----------------
__global__ __launch_bounds__(256)
void split_kernel(const float* __restrict__ in, __nv_bfloat16* __restrict__ hi,
                  __nv_bfloat16* __restrict__ lo)
{
    const size_t i = ((size_t)blockIdx.x * blockDim.x + threadIdx.x) * 4;
    float4 v = *reinterpret_cast<const float4*>(in + i);
    __nv_bfloat16 h[4], l[4];
    f2split(v.x, h[0], l[0]); f2split(v.y, h[1], l[1]);
    f2split(v.z, h[2], l[2]); f2split(v.w, h[3], l[3]);
    *reinterpret_cast<uint2*>(hi + i) = *reinterpret_cast<uint2*>(h);
    *reinterpret_cast<uint2*>(lo + i) = *reinterpret_cast<uint2*>(l);
}

// ---------------- transpose + split: fp32 [R,C] -> bf16 hi/lo [C,R] ----------------
__global__ __launch_bounds__(256)
void transpose_split_kernel(const float* __restrict__ in,
                            __nv_bfloat16* __restrict__ outH,
                            __nv_bfloat16* __restrict__ outL, int R, int C)
{
    __shared__ float t[32][33];
    int bx = blockIdx.x * 32, by = blockIdx.y * 32;
    int x = threadIdx.x & 31, y0 = threadIdx.x >> 5;
    #pragma unroll
    for (int j = 0; j < 32; j += 8)
        t[y0 + j][x] = in[(size_t)(by + y0 + j) * C + bx + x];
    __syncthreads();
    #pragma unroll
    for (int j = 0; j < 32; j += 8) {
        float v = t[x][y0 + j];
        __nv_bfloat16 h, l;
        f2split(v, h, l);
        size_t o = (size_t)(bx + y0 + j) * R + by + x;
        outH[o] = h;
        outL[o] = l;
    }
}

// ---------------- m = x @ Wm_w + b ----------------
__global__ __launch_bounds__(256)
void mvec_kernel(const float* __restrict__ x, const float* __restrict__ w,
                 const float* __restrict__ b, float* __restrict__ m)
{
    const int row  = blockIdx.x * 8 + (threadIdx.x >> 5);
    const int lane = threadIdx.x & 31;
    const float* xr = x + (size_t)row * DIM;
    float s = 0.0f;
    #pragma unroll
    for (int k = lane * 4; k < DIM; k += 128) {
        float4 xv = *reinterpret_cast<const float4*>(xr + k);
        float4 wv = *reinterpret_cast<const float4*>(w + k);
        s += xv.x * wv.x + xv.y * wv.y + xv.z * wv.z + xv.w * wv.w;
    }
    s = warpSum(s);
    if (lane == 0) m[row] = s + b[0];
}

// ---------------- merged column partial sums over qhat/khat/g ----------------
__global__ void colsum_partial3(const float* __restrict__ A0, const float* __restrict__ A1,
                                const float* __restrict__ A2, float* __restrict__ part)
{
    const int col   = blockIdx.x * blockDim.x + threadIdx.x;
    const int chunk = blockIdx.y;
    const int which = blockIdx.z;
    const float* A = which == 0 ? A0 : (which == 1 ? A1 : A2);
    const int r0 = chunk * (NT / 32);
    float s = 0.0f;
    for (int r = 0; r < NT / 32; r++) s += A[(size_t)(r0 + r) * DIM + col];
    part[((size_t)which * 32 + chunk) * DIM + col] = s;
}
__global__ void colsum_final3(const float* __restrict__ part, float* __restrict__ colred)
{
    const int col   = blockIdx.x * blockDim.x + threadIdx.x;
    const int which = blockIdx.y;
    const float* p = part + (size_t)which * 32 * DIM;
    float s = 0.0f;
    #pragma unroll
    for (int c = 0; c < 32; c++) s += p[c * DIM + col];
    const float scale = which == 2 ? 1.0f : (1.0f / NT);
    colred[which * DIM + col] = s * scale;
}

// ---------------- gate = softmax(m) over tokens ----------------
__global__ __launch_bounds__(1024)
void gate_kernel(const float* __restrict__ m, float* __restrict__ gate)
{
    __shared__ float red[32];
    const int tid = threadIdx.x, lane = tid & 31, wid = tid >> 5;
    float v[8];
    float vmax = -INFINITY;
    #pragma unroll
    for (int k = 0; k < 8; k++) { v[k] = m[tid + k * 1024]; vmax = fmaxf(vmax, v[k]); }
    vmax = warpMax(vmax);
    if (lane == 0) red[wid] = vmax;
    __syncthreads();
    float rmax = red[0];
    #pragma unroll
    for (int c = 1; c < 32; c++) rmax = fmaxf(rmax, red[c]);
    float s = 0.0f;
    #pragma unroll
    for (int k = 0; k < 8; k++) { v[k] = __expf(v[k] - rmax); s += v[k]; }
    s = warpSum(s);
    __syncthreads();
    if (lane == 0) red[wid] = s;
    __syncthreads();
    float tot = 0.0f;
    #pragma unroll
    for (int c = 0; c < 32; c++) tot += red[c];
    const float inv = 1.0f / tot;
    #pragma unroll
    for (int k = 0; k < 8; k++) gate[tid + k * 1024] = v[k] * inv;
}

// ---------------- center + split: qc=(qhat-mq)*c, kc=khat-mk -> bf16 hi/lo ----------------
__global__ __launch_bounds__(256)
void center_split_kernel(const float* __restrict__ qhat, const float* __restrict__ khat,
                         const float* __restrict__ colred, const float* __restrict__ cptr,
                         __nv_bfloat16* __restrict__ qch, __nv_bfloat16* __restrict__ qcl,
                         __nv_bfloat16* __restrict__ kch, __nv_bfloat16* __restrict__ kcl)
{
    const float c = *cptr;
    const size_t i4   = (size_t)blockIdx.x * blockDim.x + threadIdx.x;
    const size_t i    = i4 * 4;
    const int    col4 = (int)(i4 & (DIM / 4 - 1));
    float4 mq = reinterpret_cast<const float4*>(colred)[col4];
    float4 mk = reinterpret_cast<const float4*>(colred + DIM)[col4];
    float4 q = *reinterpret_cast<const float4*>(qhat + i);
    float4 k = *reinterpret_cast<const float4*>(khat + i);
    q.x = (q.x - mq.x) * c; q.y = (q.y - mq.y) * c;
    q.z = (q.z - mq.z) * c; q.w = (q.w - mq.w) * c;
    k.x -= mk.x; k.y -= mk.y; k.z -= mk.z; k.w -= mk.w;
    __nv_bfloat16 h[4], l[4];
    f2split(q.x, h[0], l[0]); f2split(q.y, h[1], l[1]);
    f2split(q.z, h[2], l[2]); f2split(q.w, h[3], l[3]);
    *reinterpret_cast<uint2*>(qch + i) = *reinterpret_cast<uint2*>(h);
    *reinterpret_cast<uint2*>(qcl + i) = *reinterpret_cast<uint2*>(l);
    f2split(k.x, h[0], l[0]); f2split(k.y, h[1], l[1]);
    f2split(k.z, h[2], l[2]); f2split(k.w, h[3], l[3]);
    *reinterpret_cast<uint2*>(kch + i) = *reinterpret_cast<uint2*>(h);
    *reinterpret_cast<uint2*>(kcl + i) = *reinterpret_cast<uint2*>(l);
}

// ---------------- row softmax of S -> bf16 hi/lo (512 threads/row) ----------------
__global__ __launch_bounds__(512)
void softmax_split_kernel(const float* __restrict__ S,
                          __nv_bfloat16* __restrict__ Sh, __nv_bfloat16* __restrict__ Sl)
{
    __shared__ float buf[NT];
    __shared__ float red[16];
    const int tid = threadIdx.x, lane = tid & 31, wid = tid >> 5;
    const float* Sr = S + (size_t)blockIdx.x * NT;
    __nv_bfloat16* ShR = Sh + (size_t)blockIdx.x * NT;
    __nv_bfloat16* SlR = Sl + (size_t)blockIdx.x * NT;

    float vmax = -INFINITY;
    #pragma unroll
    for (int k = 0; k < 4; k++) {
        int i = (tid + k * 512) * 4;
        float4 v = *reinterpret_cast<const float4*>(Sr + i);
        *reinterpret_cast<float4*>(buf + i) = v;
        vmax = fmaxf(vmax, fmaxf(fmaxf(v.x, v.y), fmaxf(v.z, v.w)));
    }
    vmax = warpMax(vmax);
    if (lane == 0) red[wid] = vmax;
    __syncthreads();
    float rmax = red[0];
    #pragma unroll
    for (int c = 1; c < 16; c++) rmax = fmaxf(rmax, red[c]);

    float ssum = 0.0f;
    #pragma unroll
    for (int k = 0; k < 4; k++) {
        int i = (tid + k * 512) * 4;
        float4 v = *reinterpret_cast<float4*>(buf + i);
        v.x = __expf(v.x - rmax); v.y = __expf(v.y - rmax);
        v.z = __expf(v.z - rmax); v.w = __expf(v.w - rmax);
        ssum += v.x + v.y + v.z + v.w;
        *reinterpret_cast<float4*>(buf + i) = v;
    }
    ssum = warpSum(ssum);
    __syncthreads();
    if (lane == 0) red[wid] = ssum;
    __syncthreads();
    float tot = 0.0f;
    #pragma unroll
    for (int c = 0; c < 16; c++) tot += red[c];
    const float inv = 1.0f / tot;
    #pragma unroll
    for (int k = 0; k < 4; k++) {
        int i = (tid + k * 512) * 4;
        float4 v = *reinterpret_cast<float4*>(buf + i);
        v.x *= inv; v.y *= inv; v.z *= inv; v.w *= inv;
        __nv_bfloat16 h[4], l[4];
        f2split(v.x, h[0], l[0]); f2split(v.y, h[1], l[1]);
        f2split(v.z, h[2], l[2]); f2split(v.w, h[3], l[3]);
        *reinterpret_cast<uint2*>(ShR + i) = *reinterpret_cast<uint2*>(h);
        *reinterpret_cast<uint2*>(SlR + i) = *reinterpret_cast<uint2*>(l);
    }
}

// ---------------- host launch ----------------
extern "C" void kernel_launch(void* const* d_in, const int* in_sizes, int n_in,
                              void* d_out, int out_size)
{
    const float* x    = (const float*)d_in[0];
    const float* Wq   = (const float*)d_in[1];
    const float* Wk   = (const float*)d_in[2];
    const float* Wg   = (const float*)d_in[3];
    const float* Wm_w = (const float*)d_in[4];
    const float* Wm_b = (const float*)d_in[5];
    const float* cs   = (const float*)d_in[6];
    float* out = (float*)d_out;

    float *qhat, *khat, *g, *S, *part, *colred, *mv, *gate;
    __nv_bfloat16 *Sh, *Sl, *xh, *xl, *qch, *qcl, *kch, *kcl, *gTh, *gTl, *WTh, *WTl;
    cudaGetSymbolAddress((void**)&qhat, d_qhat);
    cudaGetSymbolAddress((void**)&khat, d_khat);
    cudaGetSymbolAddress((void**)&g,    d_g);
    cudaGetSymbolAddress((void**)&S,    d_S);
    cudaGetSymbolAddress((void**)&Sh,   d_Sh);
    cudaGetSymbolAddress((void**)&Sl,   d_Sl);
    cudaGetSymbolAddress((void**)&xh,   d_xh);
    cudaGetSymbolAddress((void**)&xl,   d_xl);
    cudaGetSymbolAddress((void**)&qch,  d_qch);
    cudaGetSymbolAddress((void**)&qcl,  d_qcl);
    cudaGetSymbolAddress((void**)&kch,  d_kch);
    cudaGetSymbolAddress((void**)&kcl,  d_kcl);
    cudaGetSymbolAddress((void**)&gTh,  d_gTh);
    cudaGetSymbolAddress((void**)&gTl,  d_gTl);
    cudaGetSymbolAddress((void**)&WTh,  d_WTh);
    cudaGetSymbolAddress((void**)&WTl,  d_WTl);
    cudaGetSymbolAddress((void**)&part, d_part);
    cudaGetSymbolAddress((void**)&colred, d_colred);
    cudaGetSymbolAddress((void**)&mv,   d_m);
    cudaGetSymbolAddress((void**)&gate, d_gate);

    __nv_bfloat16* WqTh = WTh;
    __nv_bfloat16* WqTl = WTl;
    __nv_bfloat16* WkTh = WTh + (size_t)DIM * DIM;
    __nv_bfloat16* WkTl = WTl + (size_t)DIM * DIM;
    __nv_bfloat16* WgTh = WTh + (size_t)2 * DIM * DIM;
    __nv_bfloat16* WgTl = WTl + (size_t)2 * DIM * DIM;
    float* gsum = colred + 2 * DIM;

    cudaFuncSetAttribute(mmagemm<false>, cudaFuncAttributeMaxDynamicSharedMemorySize, GEMM_SMEM);
    cudaFuncSetAttribute(mmagemm<true>,  cudaFuncAttributeMaxDynamicSharedMemorySize, GEMM_SMEM);

    const dim3 gW(DIM / 32, DIM / 32);
    const dim3 gGT(DIM / 32, NT / 32);
    const dim3 gProj(DIM / 128, NT / 128);      // (8, 64)
    const dim3 gS(NT / 128, NT / 128);          // (64, 64)

    // 0) prepasses: weights -> transposed bf16 hi/lo ; x -> bf16 hi/lo
    transpose_split_kernel<<<gW, 256>>>(Wq, WqTh, WqTl, DIM, DIM);
    transpose_split_kernel<<<gW, 256>>>(Wk, WkTh, WkTl, DIM, DIM);
    transpose_split_kernel<<<gW, 256>>>(Wg, WgTh, WgTl, DIM, DIM);
    split_kernel<<<(NT * DIM / 4) / 256, 256>>>(x, xh, xl);

    // 1) projections
    mmagemm<false><<<gProj, 512, GEMM_SMEM>>>(xh, xl, WqTh, WqTl, qhat, DIM, nullptr, nullptr, nullptr);
    mmagemm<false><<<gProj, 512, GEMM_SMEM>>>(xh, xl, WkTh, WkTl, khat, DIM, nullptr, nullptr, nullptr);
    mmagemm<false><<<gProj, 512, GEMM_SMEM>>>(xh, xl, WgTh, WgTl, g,    DIM, nullptr, nullptr, nullptr);

    // 2) gate
    mvec_kernel<<<NT / 8, 256>>>(x, Wm_w, Wm_b, mv);
    gate_kernel<<<1, 1024>>>(mv, gate);

    // 3) merged column reductions (mq, mk, gsum)
    colsum_partial3<<<dim3(DIM / 256, 32, 3), 256>>>(qhat, khat, g, part);
    colsum_final3<<<dim3(DIM / 256, 3), 256>>>(part, colred);

    // 4) center + split to bf16 hi/lo (fold c into q)
    center_split_kernel<<<(NT * (DIM / 4)) / 256, 256>>>(qhat, khat, colred, cs,
                                                         qch, qcl, kch, kcl);

    // 5) transpose + split g -> gT bf16 hi/lo
    transpose_split_kernel<<<gGT, 256>>>(g, gTh, gTl, NT, DIM);

    // 6) S = qc @ kc^T (fp32 out)
    mmagemm<false><<<gS, 512, GEMM_SMEM>>>(qch, qcl, kch, kcl, S, DIM, nullptr, nullptr, nullptr);

    // 7) row softmax -> attn bf16 hi/lo
    softmax_split_kernel<<<NT, 512>>>(S, Sh, Sl);

    // 8) out = attn @ g + gate[i]*gsum[j] + x
    mmagemm<true><<<gProj, 512, GEMM_SMEM>>>(Sh, Sl, gTh, gTl, out, NT, gate, gsum, x);
}

// round 11
// speedup vs baseline: 1.5827x; 1.5827x over previous
#include <cuda_runtime.h>
#include <cuda_bf16.h>
#include <cstdint>

#define NT 8192      // tokens
#define DIM 1024     // model dim

// ---------------- static device scratch (no allocs allowed) ----------------
__device__ float d_qhat[(size_t)NT * DIM];
__device__ float d_khat[(size_t)NT * DIM];
__device__ float d_g   [(size_t)NT * DIM];
__device__ float d_S   [(size_t)NT * NT];            // scores fp32 (256 MB)
__device__ __nv_bfloat16 d_Sh[(size_t)NT * NT];      // attn hi (128 MB)
__device__ __nv_bfloat16 d_Sl[(size_t)NT * NT];      // attn lo (128 MB)
__device__ __nv_bfloat16 d_xh[(size_t)NT * DIM];
__device__ __nv_bfloat16 d_xl[(size_t)NT * DIM];
__device__ __nv_bfloat16 d_qch[(size_t)NT * DIM];
__device__ __nv_bfloat16 d_qcl[(size_t)NT * DIM];
__device__ __nv_bfloat16 d_kch[(size_t)NT * DIM];
__device__ __nv_bfloat16 d_kcl[(size_t)NT * DIM];
__device__ __nv_bfloat16 d_gTh[(size_t)DIM * NT];
__device__ __nv_bfloat16 d_gTl[(size_t)DIM * NT];
__device__ __nv_bfloat16 d_WTh[(size_t)3 * DIM * DIM];
__device__ __nv_bfloat16 d_WTl[(size_t)3 * DIM * DIM];
__device__ float d_part[3 * 32 * DIM];
__device__ float d_colred[3 * DIM];                  // [mq | mk | gsum]
__device__ float d_m[NT];
__device__ float d_gate[NT];

// ---------------- small helpers ----------------
__device__ __forceinline__ float warpMax(float v) {
    #pragma unroll
    for (int o = 16; o > 0; o >>= 1) v = fmaxf(v, __shfl_xor_sync(0xffffffffu, v, o));
    return v;
}
__device__ __forceinline__ float warpSum(float v) {
    #pragma unroll
    for (int o = 16; o > 0; o >>= 1) v += __shfl_xor_sync(0xffffffffu, v, o);
    return v;
}
__device__ __forceinline__ uint32_t smem_u32(const void* p) {
    uint32_t a;
    asm("{ .reg .u64 t; cvta.to.shared.u64 t, %1; cvt.u32.u64 %0, t; }" : "=r"(a) : "l"(p));
    return a;
}
__device__ __forceinline__ void f2split(float v, __nv_bfloat16& h, __nv_bfloat16& l) {
    h = __float2bfloat16_rn(v);
    l = __float2bfloat16_rn(v - __bfloat162float(h));
}

// ---------------- mma.sync / ldmatrix / cp.async wrappers (base ISA) ----------------
__device__ __forceinline__ void ldsm_x4(uint32_t& r0, uint32_t& r1, uint32_t& r2, uint32_t& r3,
                                        uint32_t addr) {
    asm volatile("ldmatrix.sync.aligned.m8n8.x4.shared.b16 {%0,%1,%2,%3}, [%4];"
                 : "=r"(r0), "=r"(r1), "=r"(r2), "=r"(r3) : "r"(addr));
}
__device__ __forceinline__ void mma_bf16(float* c, const uint32_t* a, const uint32_t* b) {
    asm volatile("mma.sync.aligned.m16n8k16.row.col.f32.bf16.bf16.f32 "
                 "{%0,%1,%2,%3}, {%4,%5,%6,%7}, {%8,%9}, {%0,%1,%2,%3};"
                 : "+f"(c[0]), "+f"(c[1]), "+f"(c[2]), "+f"(c[3])
                 : "r"(a[0]), "r"(a[1]), "r"(a[2]), "r"(a[3]), "r"(b[0]), "r"(b[1]));
}
__device__ __forceinline__ void cp16(uint32_t dst, const void* src) {
    asm volatile("cp.async.cg.shared.global [%0], [%1], 16;" :: "r"(dst), "l"(src));
}
__device__ __forceinline__ void cp_commit() {
    asm volatile("cp.async.commit_group;" ::: "memory");
}
__device__ __forceinline__ void cp_wait1() {
    asm volatile("cp.async.wait_group 1;" ::: "memory");
}

// smem tile: 128 rows x 64 bf16 (128B/row); 16B unit c in 0..7, u = c ^ (row&7)
__device__ __forceinline__ uint32_t sw_addr(uint32_t base, int row, int c) {
    return base + (uint32_t)(row * 128) + (uint32_t)((c ^ (row & 7)) << 4);
}

// ---------------- pipelined split-bf16 mma.sync GEMM ----------------
// C[M,N] = (Ah+Al)[M,K] @ (Bh+Bl)^T, B stored [N,K] row-major, bf16 hi/lo operands.
// 128x128 block, BK=64, 512 threads (16 warps, 4x4), warp tile 32x32, 3-stage cp.async.
// PROJ3: B is [3*DIM, K]; output routed to C0/C1/C2 (each [M, DIM]) by column block.
static constexpr int STAGE_BYTES = 65536;            // Ah|Al|Bh|Bl each 16 KB
static constexpr int GEMM_STAGES = 3;
static constexpr int GEMM_SMEM   = GEMM_STAGES * STAGE_BYTES;  // 192 KB

template <bool EPI, bool PROJ3>
__global__ __launch_bounds__(512, 1)
void mmagemm(const __nv_bfloat16* __restrict__ Ah, const __nv_bfloat16* __restrict__ Al,
             const __nv_bfloat16* __restrict__ Bh, const __nv_bfloat16* __restrict__ Bl,
             float* __restrict__ C0, float* __restrict__ C1, float* __restrict__ C2,
             int K, int ldc,
             const float* __restrict__ gate, const float* __restrict__ gsum,
             const float* __restrict__ xres)
{
    extern __shared__ char smem[];
    const uint32_t su = smem_u32(smem);
    const int tid  = threadIdx.x;
    const int wid  = tid >> 5, lane = tid & 31;
    const int warpM = wid >> 2, warpN = wid & 3;     // 4 x 4 warps, warp tile 32x32
    const int rowBase = blockIdx.y * 128;
    const int colBase = blockIdx.x * 128;

    // output routing
    float* Cp;
    int colOut;
    if (PROJ3) {
        const int which = colBase >> 10;             // 0,1,2 per DIM=1024 block
        Cp = which == 0 ? C0 : (which == 1 ? C1 : C2);
        colOut = colBase & 1023;
    } else {
        Cp = C0;
        colOut = colBase;
    }

    // loader: 512 threads; each does 2x16B per matrix per stage (rows lr and lr+64)
    const int lr = tid >> 3, lc = tid & 7;           // row 0..63, unit 0..7
    const __nv_bfloat16* gAh = Ah + (size_t)(rowBase + lr) * K + lc * 8;
    const __nv_bfloat16* gAl = Al + (size_t)(rowBase + lr) * K + lc * 8;
    const __nv_bfloat16* gBh = Bh + (size_t)(colBase + lr) * K + lc * 8;
    const __nv_bfloat16* gBl = Bl + (size_t)(colBase + lr) * K + lc * 8;
    const size_t rstep = (size_t)64 * K;

    const int KIT = K >> 6;

    auto issue = [&](int stage) {
        const uint32_t sb = su + (uint32_t)(stage % 3) * STAGE_BYTES;
        const int k0 = stage << 6;
        cp16(sw_addr(sb,          lr,      lc), gAh + k0);
        cp16(sw_addr(sb,          lr + 64, lc), gAh + rstep + k0);
        cp16(sw_addr(sb + 16384u, lr,      lc), gAl + k0);
        cp16(sw_addr(sb + 16384u, lr + 64, lc), gAl + rstep + k0);
        cp16(sw_addr(sb + 32768u, lr,      lc), gBh + k0);
        cp16(sw_addr(sb + 32768u, lr + 64, lc), gBh + rstep + k0);
        cp16(sw_addr(sb + 49152u, lr,      lc), gBl + k0);
        cp16(sw_addr(sb + 49152u, lr + 64, lc), gBl + rstep + k0);
    };

    // prologue: stages 0..1
    issue(0); cp_commit();
    if (KIT > 1) issue(1);
    cp_commit();

    float acc[2][4][4];
    #pragma unroll
    for (int i = 0; i < 2; i++)
        #pragma unroll
        for (int j = 0; j < 4; j++)
            #pragma unroll
            for (int k = 0; k < 4; k++) acc[i][j][k] = 0.0f;

    // ldmatrix lane addressing
    const int aRow = warpM * 32 + (lane & 15);       // + tm*16
    const int aC   = lane >> 4;                      // 0/1
    const int bRow = warpN * 32 + (lane & 7) + ((lane >> 4) << 3);  // + pair*16
    const int bC   = (lane >> 3) & 1;                // 0/1

    for (int it = 0; it < KIT; ++it) {
        cp_wait1();
        __syncthreads();
        if (it + 2 < KIT) issue(it + 2);
        cp_commit();                                  // empty commit keeps count uniform

        const uint32_t sb = su + (uint32_t)(it % 3) * STAGE_BYTES;
        #pragma unroll
        for (int kh = 0; kh < 4; kh++) {
            uint32_t ah[2][4], al[2][4], bfh[4][2], bfl[4][2];
            #pragma unroll
            for (int tm = 0; tm < 2; tm++) {
                ldsm_x4(ah[tm][0], ah[tm][1], ah[tm][2], ah[tm][3],
                        sw_addr(sb, aRow + tm * 16, kh * 2 + aC));
                ldsm_x4(al[tm][0], al[tm][1], al[tm][2], al[tm][3],
                        sw_addr(sb + 16384u, aRow + tm * 16, kh * 2 + aC));
            }
            #pragma unroll
            for (int p = 0; p < 2; p++) {            // n-tile pairs (2p, 2p+1)
                ldsm_x4(bfh[2*p][0], bfh[2*p][1], bfh[2*p+1][0], bfh[2*p+1][1],
                        sw_addr(sb + 32768u, bRow + p * 16, kh * 2 + bC));
                ldsm_x4(bfl[2*p][0], bfl[2*p][1], bfl[2*p+1][0], bfl[2*p+1][1],
                        sw_addr(sb + 49152u, bRow + p * 16, kh * 2 + bC));
            }
            #pragma unroll
            for (int tm = 0; tm < 2; tm++)
                #pragma unroll
                for (int tn = 0; tn < 4; tn++) {
                    mma_bf16(acc[tm][tn], ah[tm], bfh[tn]);
                    mma_bf16(acc[tm][tn], ah[tm], bfl[tn]);
                    mma_bf16(acc[tm][tn], al[tm], bfh[tn]);
                }
        }
    }

    // epilogue: direct stores
    const int g  = lane >> 2;
    const int t4 = lane & 3;
    #pragma unroll
    for (int tm = 0; tm < 2; tm++) {
        const int row = rowBase + warpM * 32 + tm * 16 + g;
        #pragma unroll
        for (int tn = 0; tn < 4; tn++) {
            const int col = colOut + warpN * 32 + tn * 8 + t4 * 2;
            float v0 = acc[tm][tn][0], v1 = acc[tm][tn][1];
            float v2 = acc[tm][tn][2], v3 = acc[tm][tn][3];
            if (EPI) {
                const float gt0 = gate[row], gt8 = gate[row + 8];
                const float2 gs = *reinterpret_cast<const float2*>(gsum + col);
                const float2 x0 = *reinterpret_cast<const float2*>(
                    xres + (size_t)row * ldc + col);
                const float2 x8 = *reinterpret_cast<const float2*>(
                    xres + (size_t)(row + 8) * ldc + col);
                v0 += gt0 * gs.x + x0.x;  v1 += gt0 * gs.y + x0.y;
                v2 += gt8 * gs.x + x8.x;  v3 += gt8 * gs.y + x8.y;
            }
            *reinterpret_cast<float2*>(Cp + (size_t)row * ldc + col) = make_float2(v0, v1);
            *reinterpret_cast<float2*>(Cp + (size_t)(row + 8) * ldc + col) = make_float2(v2, v3);
        }
    }
}

// ---------------- elementwise split: fp32 -> bf16 hi/lo ----------------
__global__ __launch_bounds__(256)
void split_kernel(const float* __restrict__ in, __nv_bfloat16* __restrict__ hi,
                  __nv_bfloat16* __restrict__ lo)
{
    const size_t i = ((size_t)blockIdx.x * blockDim.x + threadIdx.x) * 4;
    float4 v = *reinterpret_cast<const float4*>(in + i);
    __nv_bfloat16 h[4], l[4];
    f2split(v.x, h[0], l[0]); f2split(v.y, h[1], l[1]);
    f2split(v.z, h[2], l[2]); f2split(v.w, h[3], l[3]);
    *reinterpret_cast<uint2*>(hi + i) = *reinterpret_cast<uint2*>(h);
    *reinterpret_cast<uint2*>(lo + i) = *reinterpret_cast<uint2*>(l);
}

// ---------------- transpose + split: fp32 [R,C] -> bf16 hi/lo [C,R] ----------------
__global__ __launch_bounds__(256)
void transpose_split_kernel(const float* __restrict__ in,
                            __nv_bfloat16* __restrict__ outH,
                            __nv_bfloat16* __restrict__ outL, int R, int C)
{
    __shared__ float t[32][33];
    int bx = blockIdx.x * 32, by = blockIdx.y * 32;
    int x = threadIdx.x & 31, y0 = threadIdx.x >> 5;
    #pragma unroll
    for (int j = 0; j < 32; j += 8)
        t[y0 + j][x] = in[(size_t)(by + y0 + j) * C + bx + x];
    __syncthreads();
    #pragma unroll
    for (int j = 0; j < 32; j += 8) {
        float v = t[x][y0 + j];
        __nv_bfloat16 h, l;
        f2split(v, h, l);
        size_t o = (size_t)(bx + y0 + j) * R + by + x;
        outH[o] = h;
        outL[o] = l;
    }
}

// ---------------- m = x @ Wm_w + b ----------------
__global__ __launch_bounds__(256)
void mvec_kernel(const float* __restrict__ x, const float* __restrict__ w,
                 const float* __restrict__ b, float* __restrict__ m)
{
    const int row  = blockIdx.x * 8 + (threadIdx.x >> 5);
    const int lane = threadIdx.x & 31;
    const float* xr = x + (size_t)row * DIM;
    float s = 0.0f;
    #pragma unroll
    for (int k = lane * 4; k < DIM; k += 128) {
        float4 xv = *reinterpret_cast<const float4*>(xr + k);
        float4 wv = *reinterpret_cast<const float4*>(w + k);
        s += xv.x * wv.x + xv.y * wv.y + xv.z * wv.z + xv.w * wv.w;
    }
    s = warpSum(s);
    if (lane == 0) m[row] = s + b[0];
}

// ---------------- merged column partial sums over qhat/khat/g ----------------
__global__ void colsum_partial3(const float* __restrict__ A0, const float* __restrict__ A1,
                                const float* __restrict__ A2, float* __restrict__ part)
{
    const int col   = blockIdx.x * blockDim.x + threadIdx.x;
    const int chunk = blockIdx.y;
    const int which = blockIdx.z;
    const float* A = which == 0 ? A0 : (which == 1 ? A1 : A2);
    const int r0 = chunk * (NT / 32);
    float s = 0.0f;
    for (int r = 0; r < NT / 32; r++) s += A[(size_t)(r0 + r) * DIM + col];
    part[((size_t)which * 32 + chunk) * DIM + col] = s;
}
__global__ void colsum_final3(const float* __restrict__ part, float* __restrict__ colred)
{
    const int col   = blockIdx.x * blockDim.x + threadIdx.x;
    const int which = blockIdx.y;
    const float* p = part + (size_t)which * 32 * DIM;
    float s = 0.0f;
    #pragma unroll
    for (int c = 0; c < 32; c++) s += p[c * DIM + col];
    const float scale = which == 2 ? 1.0f : (1.0f / NT);
    colred[which * DIM + col] = s * scale;
}

// ---------------- gate = softmax(m) over tokens ----------------
__global__ __launch_bounds__(1024)
void gate_kernel(const float* __restrict__ m, float* __restrict__ gate)
{
    __shared__ float red[32];
    const int tid = threadIdx.x, lane = tid & 31, wid = tid >> 5;
    float v[8];
    float vmax = -INFINITY;
    #pragma unroll
    for (int k = 0; k < 8; k++) { v[k] = m[tid + k * 1024]; vmax = fmaxf(vmax, v[k]); }
    vmax = warpMax(vmax);
    if (lane == 0) red[wid] = vmax;
    __syncthreads();
    float rmax = red[0];
    #pragma unroll
    for (int c = 1; c < 32; c++) rmax = fmaxf(rmax, red[c]);
    float s = 0.0f;
    #pragma unroll
    for (int k = 0; k < 8; k++) { v[k] = __expf(v[k] - rmax); s += v[k]; }
    s = warpSum(s);
    __syncthreads();
    if (lane == 0) red[wid] = s;
    __syncthreads();
    float tot = 0.0f;
    #pragma unroll
    for (int c = 0; c < 32; c++) tot += red[c];
    const float inv = 1.0f / tot;
    #pragma unroll
    for (int k = 0; k < 8; k++) gate[tid + k * 1024] = v[k] * inv;
}

// ---------------- center + split: qc=(qhat-mq)*c, kc=khat-mk -> bf16 hi/lo ----------------
__global__ __launch_bounds__(256)
void center_split_kernel(const float* __restrict__ qhat, const float* __restrict__ khat,
                         const float* __restrict__ colred, const float* __restrict__ cptr,
                         __nv_bfloat16* __restrict__ qch, __nv_bfloat16* __restrict__ qcl,
                         __nv_bfloat16* __restrict__ kch, __nv_bfloat16* __restrict__ kcl)
{
    const float c = *cptr;
    const size_t i4   = (size_t)blockIdx.x * blockDim.x + threadIdx.x;
    const size_t i    = i4 * 4;
    const int    col4 = (int)(i4 & (DIM / 4 - 1));
    float4 mq = reinterpret_cast<const float4*>(colred)[col4];
    float4 mk = reinterpret_cast<const float4*>(colred + DIM)[col4];
    float4 q = *reinterpret_cast<const float4*>(qhat + i);
    float4 k = *reinterpret_cast<const float4*>(khat + i);
    q.x = (q.x - mq.x) * c; q.y = (q.y - mq.y) * c;
    q.z = (q.z - mq.z) * c; q.w = (q.w - mq.w) * c;
    k.x -= mk.x; k.y -= mk.y; k.z -= mk.z; k.w -= mk.w;
    __nv_bfloat16 h[4], l[4];
    f2split(q.x, h[0], l[0]); f2split(q.y, h[1], l[1]);
    f2split(q.z, h[2], l[2]); f2split(q.w, h[3], l[3]);
    *reinterpret_cast<uint2*>(qch + i) = *reinterpret_cast<uint2*>(h);
    *reinterpret_cast<uint2*>(qcl + i) = *reinterpret_cast<uint2*>(l);
    f2split(k.x, h[0], l[0]); f2split(k.y, h[1], l[1]);
    f2split(k.z, h[2], l[2]); f2split(k.w, h[3], l[3]);
    *reinterpret_cast<uint2*>(kch + i) = *reinterpret_cast<uint2*>(h);
    *reinterpret_cast<uint2*>(kcl + i) = *reinterpret_cast<uint2*>(l);
}

// ---------------- row softmax of S -> bf16 hi/lo (512 threads/row) ----------------
__global__ __launch_bounds__(512)
void softmax_split_kernel(const float* __restrict__ S,
                          __nv_bfloat16* __restrict__ Sh, __nv_bfloat16* __restrict__ Sl)
{
    __shared__ float buf[NT];
    __shared__ float red[16];
    const int tid = threadIdx.x, lane = tid & 31, wid = tid >> 5;
    const float* Sr = S + (size_t)blockIdx.x * NT;
    __nv_bfloat16* ShR = Sh + (size_t)blockIdx.x * NT;
    __nv_bfloat16* SlR = Sl + (size_t)blockIdx.x * NT;

    float vmax = -INFINITY;
    #pragma unroll
    for (int k = 0; k < 4; k++) {
        int i = (tid + k * 512) * 4;
        float4 v = *reinterpret_cast<const float4*>(Sr + i);
        *reinterpret_cast<float4*>(buf + i) = v;
        vmax = fmaxf(vmax, fmaxf(fmaxf(v.x, v.y), fmaxf(v.z, v.w)));
    }
    vmax = warpMax(vmax);
    if (lane == 0) red[wid] = vmax;
    __syncthreads();
    float rmax = red[0];
    #pragma unroll
    for (int c = 1; c < 16; c++) rmax = fmaxf(rmax, red[c]);

    float ssum = 0.0f;
    #pragma unroll
    for (int k = 0; k < 4; k++) {
        int i = (tid + k * 512) * 4;
        float4 v = *reinterpret_cast<float4*>(buf + i);
        v.x = __expf(v.x - rmax); v.y = __expf(v.y - rmax);
        v.z = __expf(v.z - rmax); v.w = __expf(v.w - rmax);
        ssum += v.x + v.y + v.z + v.w;
        *reinterpret_cast<float4*>(buf + i) = v;
    }
    ssum = warpSum(ssum);
    __syncthreads();
    if (lane == 0) red[wid] = ssum;
    __syncthreads();
    float tot = 0.0f;
    #pragma unroll
    for (int c = 0; c < 16; c++) tot += red[c];
    const float inv = 1.0f / tot;
    #pragma unroll
    for (int k = 0; k < 4; k++) {
        int i = (tid + k * 512) * 4;
        float4 v = *reinterpret_cast<float4*>(buf + i);
        v.x *= inv; v.y *= inv; v.z *= inv; v.w *= inv;
        __nv_bfloat16 h[4], l[4];
        f2split(v.x, h[0], l[0]); f2split(v.y, h[1], l[1]);
        f2split(v.z, h[2], l[2]); f2split(v.w, h[3], l[3]);
        *reinterpret_cast<uint2*>(ShR + i) = *reinterpret_cast<uint2*>(h);
        *reinterpret_cast<uint2*>(SlR + i) = *reinterpret_cast<uint2*>(l);
    }
}

// ---------------- host launch ----------------
extern "C" void kernel_launch(void* const* d_in, const int* in_sizes, int n_in,
                              void* d_out, int out_size)
{
    const float* x    = (const float*)d_in[0];
    const float* Wq   = (const float*)d_in[1];
    const float* Wk   = (const float*)d_in[2];
    const float* Wg   = (const float*)d_in[3];
    const float* Wm_w = (const float*)d_in[4];
    const float* Wm_b = (const float*)d_in[5];
    const float* cs   = (const float*)d_in[6];
    float* out = (float*)d_out;

    float *qhat, *khat, *g, *S, *part, *colred, *mv, *gate;
    __nv_bfloat16 *Sh, *Sl, *xh, *xl, *qch, *qcl, *kch, *kcl, *gTh, *gTl, *WTh, *WTl;
    cudaGetSymbolAddress((void**)&qhat, d_qhat);
    cudaGetSymbolAddress((void**)&khat, d_khat);
    cudaGetSymbolAddress((void**)&g,    d_g);
    cudaGetSymbolAddress((void**)&S,    d_S);
    cudaGetSymbolAddress((void**)&Sh,   d_Sh);
    cudaGetSymbolAddress((void**)&Sl,   d_Sl);
    cudaGetSymbolAddress((void**)&xh,   d_xh);
    cudaGetSymbolAddress((void**)&xl,   d_xl);
    cudaGetSymbolAddress((void**)&qch,  d_qch);
    cudaGetSymbolAddress((void**)&qcl,  d_qcl);
    cudaGetSymbolAddress((void**)&kch,  d_kch);
    cudaGetSymbolAddress((void**)&kcl,  d_kcl);
    cudaGetSymbolAddress((void**)&gTh,  d_gTh);
    cudaGetSymbolAddress((void**)&gTl,  d_gTl);
    cudaGetSymbolAddress((void**)&WTh,  d_WTh);
    cudaGetSymbolAddress((void**)&WTl,  d_WTl);
    cudaGetSymbolAddress((void**)&part, d_part);
    cudaGetSymbolAddress((void**)&colred, d_colred);
    cudaGetSymbolAddress((void**)&mv,   d_m);
    cudaGetSymbolAddress((void**)&gate, d_gate);

    __nv_bfloat16* WqTh = WTh;
    __nv_bfloat16* WqTl = WTl;
    __nv_bfloat16* WkTh = WTh + (size_t)DIM * DIM;
    __nv_bfloat16* WkTl = WTl + (size_t)DIM * DIM;
    __nv_bfloat16* WgTh = WTh + (size_t)2 * DIM * DIM;
    __nv_bfloat16* WgTl = WTl + (size_t)2 * DIM * DIM;
    float* gsum = colred + 2 * DIM;

    cudaFuncSetAttribute(mmagemm<false, true>,  cudaFuncAttributeMaxDynamicSharedMemorySize, GEMM_SMEM);
    cudaFuncSetAttribute(mmagemm<false, false>, cudaFuncAttributeMaxDynamicSharedMemorySize, GEMM_SMEM);
    cudaFuncSetAttribute(mmagemm<true, false>,  cudaFuncAttributeMaxDynamicSharedMemorySize, GEMM_SMEM);

    const dim3 gW(DIM / 32, DIM / 32);
    const dim3 gGT(DIM / 32, NT / 32);
    const dim3 gProj3(3 * DIM / 128, NT / 128);  // (24, 64) fused q/k/g projections
    const dim3 gOut(DIM / 128, NT / 128);        // (8, 64)
    const dim3 gS(NT / 128, NT / 128);           // (64, 64)

    // 0) prepasses: weights -> transposed bf16 hi/lo ; x -> bf16 hi/lo
    transpose_split_kernel<<<gW, 256>>>(Wq, WqTh, WqTl, DIM, DIM);
    transpose_split_kernel<<<gW, 256>>>(Wk, WkTh, WkTl, DIM, DIM);
    transpose_split_kernel<<<gW, 256>>>(Wg, WgTh, WgTl, DIM, DIM);
    split_kernel<<<(NT * DIM / 4) / 256, 256>>>(x, xh, xl);

    // 1) fused projections: [qhat | khat | g] = x @ [Wq | Wk | Wg]
    mmagemm<false, true><<<gProj3, 512, GEMM_SMEM>>>(xh, xl, WTh, WTl,
                                                     qhat, khat, g, DIM, DIM,
                                                     nullptr, nullptr, nullptr);

    // 2) gate
    mvec_kernel<<<NT / 8, 256>>>(x, Wm_w, Wm_b, mv);
    gate_kernel<<<1, 1024>>>(mv, gate);

    // 3) merged column reductions (mq, mk, gsum)
    colsum_partial3<<<dim3(DIM / 256, 32, 3), 256>>>(qhat, khat, g, part);
    colsum_final3<<<dim3(DIM / 256, 3), 256>>>(part, colred);

    // 4) center + split to bf16 hi/lo (fold c into q)
    center_split_kernel<<<(NT * (DIM / 4)) / 256, 256>>>(qhat, khat, colred, cs,
                                                         qch, qcl, kch, kcl);

    // 5) transpose + split g -> gT bf16 hi/lo
    transpose_split_kernel<<<gGT, 256>>>(g, gTh, gTl, NT, DIM);

    // 6) S = qc @ kc^T (fp32 out)
    mmagemm<false, false><<<gS, 512, GEMM_SMEM>>>(qch, qcl, kch, kcl,
                                                  S, nullptr, nullptr, DIM, NT,
                                                  nullptr, nullptr, nullptr);

    // 7) row softmax -> attn bf16 hi/lo
    softmax_split_kernel<<<NT, 512>>>(S, Sh, Sl);

    // 8) out = attn @ g + gate[i]*gsum[j] + x
    mmagemm<true, false><<<gOut, 512, GEMM_SMEM>>>(Sh, Sl, gTh, gTl,
                                                   out, nullptr, nullptr, NT, DIM,
                                                   gate, gsum, x);
}

// round 15
// speedup vs baseline: 2.0636x; 1.3038x over previous
#include <cuda_runtime.h>
#include <cuda_bf16.h>
#include <cstdint>

#define NT 8192      // tokens
#define DIM 1024     // model dim

// ---------------- static device scratch (no allocs allowed) ----------------
__device__ float d_qhat[(size_t)NT * DIM];
__device__ float d_khat[(size_t)NT * DIM];
__device__ float d_g   [(size_t)NT * DIM];
__device__ float d_S   [(size_t)NT * NT];            // scores fp32 (256 MB)
__device__ __nv_bfloat16 d_Sh[(size_t)NT * NT];      // attn bf16 (128 MB)
__device__ __nv_bfloat16 d_xh[(size_t)NT * DIM];
__device__ __nv_bfloat16 d_xl[(size_t)NT * DIM];
__device__ __nv_bfloat16 d_qch[(size_t)NT * DIM];
__device__ __nv_bfloat16 d_qcl[(size_t)NT * DIM];
__device__ __nv_bfloat16 d_kch[(size_t)NT * DIM];
__device__ __nv_bfloat16 d_kcl[(size_t)NT * DIM];
__device__ __nv_bfloat16 d_gTh[(size_t)DIM * NT];
__device__ __nv_bfloat16 d_WTh[(size_t)3 * DIM * DIM];
__device__ __nv_bfloat16 d_WTl[(size_t)3 * DIM * DIM];
__device__ float d_part[3 * 32 * DIM];
__device__ float d_colred[3 * DIM];                  // [mq | mk | gsum]
__device__ float d_m[NT];
__device__ float d_gate[NT];

// ---------------- small helpers ----------------
__device__ __forceinline__ float warpMax(float v) {
    #pragma unroll
    for (int o = 16; o > 0; o >>= 1) v = fmaxf(v, __shfl_xor_sync(0xffffffffu, v, o));
    return v;
}
__device__ __forceinline__ float warpSum(float v) {
    #pragma unroll
    for (int o = 16; o > 0; o >>= 1) v += __shfl_xor_sync(0xffffffffu, v, o);
    return v;
}
__device__ __forceinline__ uint32_t smem_u32(const void* p) {
    uint32_t a;
    asm("{ .reg .u64 t; cvta.to.shared.u64 t, %1; cvt.u32.u64 %0, t; }" : "=r"(a) : "l"(p));
    return a;
}
__device__ __forceinline__ void f2split(float v, __nv_bfloat16& h, __nv_bfloat16& l) {
    h = __float2bfloat16_rn(v);
    l = __float2bfloat16_rn(v - __bfloat162float(h));
}

// ---------------- mma.sync / ldmatrix / cp.async wrappers (base ISA) ----------------
__device__ __forceinline__ void ldsm_x4(uint32_t& r0, uint32_t& r1, uint32_t& r2, uint32_t& r3,
                                        uint32_t addr) {
    asm volatile("ldmatrix.sync.aligned.m8n8.x4.shared.b16 {%0,%1,%2,%3}, [%4];"
                 : "=r"(r0), "=r"(r1), "=r"(r2), "=r"(r3) : "r"(addr));
}
__device__ __forceinline__ void mma_bf16(float* c, const uint32_t* a, const uint32_t* b) {
    asm volatile("mma.sync.aligned.m16n8k16.row.col.f32.bf16.bf16.f32 "
                 "{%0,%1,%2,%3}, {%4,%5,%6,%7}, {%8,%9}, {%0,%1,%2,%3};"
                 : "+f"(c[0]), "+f"(c[1]), "+f"(c[2]), "+f"(c[3])
                 : "r"(a[0]), "r"(a[1]), "r"(a[2]), "r"(a[3]), "r"(b[0]), "r"(b[1]));
}
__device__ __forceinline__ void cp16(uint32_t dst, const void* src) {
    asm volatile("cp.async.cg.shared.global [%0], [%1], 16;" :: "r"(dst), "l"(src));
}
__device__ __forceinline__ void cp_commit() {
    asm volatile("cp.async.commit_group;" ::: "memory");
}
__device__ __forceinline__ void cp_wait1() {
    asm volatile("cp.async.wait_group 1;" ::: "memory");
}

// smem tile: 128 rows x 64 bf16 (128B/row); 16B unit c in 0..7, u = c ^ (row&7)
__device__ __forceinline__ uint32_t sw_addr(uint32_t base, int row, int c) {
    return base + (uint32_t)(row * 128) + (uint32_t)((c ^ (row & 7)) << 4);
}

// ---------------- pipelined split-bf16 mma.sync GEMM ----------------
// C[M,N] = A[M,K] @ B^T, B stored [N,K] row-major.
// TERMS=3: A=(Ah+Al), B=(Bh+Bl), 3-term split (Ah·Bh + Ah·Bl + Al·Bh).
// TERMS=1: plain bf16 GEMM on Ah·Bh.
// 128x128 block, BK=64, 512 threads (16 warps, 4x4), warp tile 32x32, 3-stage cp.async.
// PROJ3: B is [3*DIM, K]; output routed to C0/C1/C2 (each [M, DIM]) by column block.
template <int TERMS>
struct StageCfg {
    static constexpr uint32_t AL = 16384u;
    static constexpr uint32_t BH = (TERMS == 3) ? 32768u : 16384u;
    static constexpr uint32_t BL = 49152u;
    static constexpr uint32_t STAGE = (TERMS == 3) ? 65536u : 32768u;
};
static constexpr int GEMM_SMEM3 = 3 * 65536;   // 192 KB
static constexpr int GEMM_SMEM1 = 3 * 32768;   // 96 KB

template <bool EPI, bool PROJ3, int TERMS>
__global__ __launch_bounds__(512, 1)
void mmagemm(const __nv_bfloat16* __restrict__ Ah, const __nv_bfloat16* __restrict__ Al,
             const __nv_bfloat16* __restrict__ Bh, const __nv_bfloat16* __restrict__ Bl,
             float* __restrict__ C0, float* __restrict__ C1, float* __restrict__ C2,
             int K, int ldc,
             const float* __restrict__ gate, const float* __restrict__ gsum,
             const float* __restrict__ xres)
{
    using CFG = StageCfg<TERMS>;
    extern __shared__ char smem[];
    const uint32_t su = smem_u32(smem);
    const int tid  = threadIdx.x;
    const int wid  = tid >> 5, lane = tid & 31;
    const int warpM = wid >> 2, warpN = wid & 3;     // 4 x 4 warps, warp tile 32x32
    const int rowBase = blockIdx.y * 128;
    const int colBase = blockIdx.x * 128;

    // output routing
    float* Cp;
    int colOut;
    if (PROJ3) {
        const int which = colBase >> 10;             // 0,1,2 per DIM=1024 block
        Cp = which == 0 ? C0 : (which == 1 ? C1 : C2);
        colOut = colBase & 1023;
    } else {
        Cp = C0;
        colOut = colBase;
    }

    // loader: 512 threads; each does 2x16B per matrix per stage (rows lr and lr+64)
    const int lr = tid >> 3, lc = tid & 7;           // row 0..63, unit 0..7
    const __nv_bfloat16* gAh = Ah + (size_t)(rowBase + lr) * K + lc * 8;
    const __nv_bfloat16* gAl = TERMS == 3 ? Al + (size_t)(rowBase + lr) * K + lc * 8 : nullptr;
    const __nv_bfloat16* gBh = Bh + (size_t)(colBase + lr) * K + lc * 8;
    const __nv_bfloat16* gBl = TERMS == 3 ? Bl + (size_t)(colBase + lr) * K + lc * 8 : nullptr;
    const size_t rstep = (size_t)64 * K;

    const int KIT = K >> 6;

    auto issue = [&](int stage) {
        const uint32_t sb = su + (uint32_t)(stage % 3) * CFG::STAGE;
        const int k0 = stage << 6;
        cp16(sw_addr(sb,           lr,      lc), gAh + k0);
        cp16(sw_addr(sb,           lr + 64, lc), gAh + rstep + k0);
        cp16(sw_addr(sb + CFG::BH, lr,      lc), gBh + k0);
        cp16(sw_addr(sb + CFG::BH, lr + 64, lc), gBh + rstep + k0);
        if (TERMS == 3) {
            cp16(sw_addr(sb + CFG::AL, lr,      lc), gAl + k0);
            cp16(sw_addr(sb + CFG::AL, lr + 64, lc), gAl + rstep + k0);
            cp16(sw_addr(sb + CFG::BL, lr,      lc), gBl + k0);
            cp16(sw_addr(sb + CFG::BL, lr + 64, lc), gBl + rstep + k0);
        }
    };

    // prologue: stages 0..1
    issue(0); cp_commit();
    if (KIT > 1) issue(1);
    cp_commit();

    float acc[2][4][4];
    #pragma unroll
    for (int i = 0; i < 2; i++)
        #pragma unroll
        for (int j = 0; j < 4; j++)
            #pragma unroll
            for (int k = 0; k < 4; k++) acc[i][j][k] = 0.0f;

    // ldmatrix lane addressing
    const int aRow = warpM * 32 + (lane & 15);       // + tm*16
    const int aC   = lane >> 4;                      // 0/1
    const int bRow = warpN * 32 + (lane & 7) + ((lane >> 4) << 3);  // + pair*16
    const int bC   = (lane >> 3) & 1;                // 0/1

    for (int it = 0; it < KIT; ++it) {
        cp_wait1();
        __syncthreads();
        if (it + 2 < KIT) issue(it + 2);
        cp_commit();                                  // empty commit keeps count uniform

        const uint32_t sb = su + (uint32_t)(it % 3) * CFG::STAGE;
        #pragma unroll
        for (int kh = 0; kh < 4; kh++) {
            uint32_t ah[2][4], al[2][4], bfh[4][2], bfl[4][2];
            #pragma unroll
            for (int tm = 0; tm < 2; tm++) {
                ldsm_x4(ah[tm][0], ah[tm][1], ah[tm][2], ah[tm][3],
                        sw_addr(sb, aRow + tm * 16, kh * 2 + aC));
                if (TERMS == 3)
                    ldsm_x4(al[tm][0], al[tm][1], al[tm][2], al[tm][3],
                            sw_addr(sb + CFG::AL, aRow + tm * 16, kh * 2 + aC));
            }
            #pragma unroll
            for (int p = 0; p < 2; p++) {            // n-tile pairs (2p, 2p+1)
                ldsm_x4(bfh[2*p][0], bfh[2*p][1], bfh[2*p+1][0], bfh[2*p+1][1],
                        sw_addr(sb + CFG::BH, bRow + p * 16, kh * 2 + bC));
                if (TERMS == 3)
                    ldsm_x4(bfl[2*p][0], bfl[2*p][1], bfl[2*p+1][0], bfl[2*p+1][1],
                            sw_addr(sb + CFG::BL, bRow + p * 16, kh * 2 + bC));
            }
            #pragma unroll
            for (int tm = 0; tm < 2; tm++)
                #pragma unroll
                for (int tn = 0; tn < 4; tn++) {
                    mma_bf16(acc[tm][tn], ah[tm], bfh[tn]);
                    if (TERMS == 3) {
                        mma_bf16(acc[tm][tn], ah[tm], bfl[tn]);
                        mma_bf16(acc[tm][tn], al[tm], bfh[tn]);
                    }
                }
        }
    }

    // epilogue: direct stores
    const int g  = lane >> 2;
    const int t4 = lane & 3;
    #pragma unroll
    for (int tm = 0; tm < 2; tm++) {
        const int row = rowBase + warpM * 32 + tm * 16 + g;
        #pragma unroll
        for (int tn = 0; tn < 4; tn++) {
            const int col = colOut + warpN * 32 + tn * 8 + t4 * 2;
            float v0 = acc[tm][tn][0], v1 = acc[tm][tn][1];
            float v2 = acc[tm][tn][2], v3 = acc[tm][tn][3];
            if (EPI) {
                const float gt0 = gate[row], gt8 = gate[row + 8];
                const float2 gs = *reinterpret_cast<const float2*>(gsum + col);
                const float2 x0 = *reinterpret_cast<const float2*>(
                    xres + (size_t)row * ldc + col);
                const float2 x8 = *reinterpret_cast<const float2*>(
                    xres + (size_t)(row + 8) * ldc + col);
                v0 += gt0 * gs.x + x0.x;  v1 += gt0 * gs.y + x0.y;
                v2 += gt8 * gs.x + x8.x;  v3 += gt8 * gs.y + x8.y;
            }
            *reinterpret_cast<float2*>(Cp + (size_t)row * ldc + col) = make_float2(v0, v1);
            *reinterpret_cast<float2*>(Cp + (size_t)(row + 8) * ldc + col) = make_float2(v2, v3);
        }
    }
}

// ---------------- elementwise split: fp32 -> bf16 hi/lo ----------------
__global__ __launch_bounds__(256)
void split_kernel(const float* __restrict__ in, __nv_bfloat16* __restrict__ hi,
                  __nv_bfloat16* __restrict__ lo)
{
    const size_t i = ((size_t)blockIdx.x * blockDim.x + threadIdx.x) * 4;
    float4 v = *reinterpret_cast<const float4*>(in + i);
    __nv_bfloat16 h[4], l[4];
    f2split(v.x, h[0], l[0]); f2split(v.y, h[1], l[1]);
    f2split(v.z, h[2], l[2]); f2split(v.w, h[3], l[3]);
    *reinterpret_cast<uint2*>(hi + i) = *reinterpret_cast<uint2*>(h);
    *reinterpret_cast<uint2*>(lo + i) = *reinterpret_cast<uint2*>(l);
}

// ---------------- transpose + split: fp32 [R,C] -> bf16 hi(/lo) [C,R] ----------------
template <bool WRITE_LO>
__global__ __launch_bounds__(256)
void transpose_split_kernel(const float* __restrict__ in,
                            __nv_bfloat16* __restrict__ outH,
                            __nv_bfloat16* __restrict__ outL, int R, int C)
{
    __shared__ float t[32][33];
    int bx = blockIdx.x * 32, by = blockIdx.y * 32;
    int x = threadIdx.x & 31, y0 = threadIdx.x >> 5;
    #pragma unroll
    for (int j = 0; j < 32; j += 8)
        t[y0 + j][x] = in[(size_t)(by + y0 + j) * C + bx + x];
    __syncthreads();
    #pragma unroll
    for (int j = 0; j < 32; j += 8) {
        float v = t[x][y0 + j];
        __nv_bfloat16 h, l;
        f2split(v, h, l);
        size_t o = (size_t)(bx + y0 + j) * R + by + x;
        outH[o] = h;
        if (WRITE_LO) outL[o] = l;
    }
}

// ---------------- m = x @ Wm_w + b ----------------
__global__ __launch_bounds__(256)
void mvec_kernel(const float* __restrict__ x, const float* __restrict__ w,
                 const float* __restrict__ b, float* __restrict__ m)
{
    const int row  = blockIdx.x * 8 + (threadIdx.x >> 5);
    const int lane = threadIdx.x & 31;
    const float* xr = x + (size_t)row * DIM;
    float s = 0.0f;
    #pragma unroll
    for (int k = lane * 4; k < DIM; k += 128) {
        float4 xv = *reinterpret_cast<const float4*>(xr + k);
        float4 wv = *reinterpret_cast<const float4*>(w + k);
        s += xv.x * wv.x + xv.y * wv.y + xv.z * wv.z + xv.w * wv.w;
    }
    s = warpSum(s);
    if (lane == 0) m[row] = s + b[0];
}

// ---------------- merged column partial sums over qhat/khat/g ----------------
__global__ void colsum_partial3(const float* __restrict__ A0, const float* __restrict__ A1,
                                const float* __restrict__ A2, float* __restrict__ part)
{
    const int col   = blockIdx.x * blockDim.x + threadIdx.x;
    const int chunk = blockIdx.y;
    const int which = blockIdx.z;
    const float* A = which == 0 ? A0 : (which == 1 ? A1 : A2);
    const int r0 = chunk * (NT / 32);
    float s = 0.0f;
    for (int r = 0; r < NT / 32; r++) s += A[(size_t)(r0 + r) * DIM + col];
    part[((size_t)which * 32 + chunk) * DIM + col] = s;
}
__global__ void colsum_final3(const float* __restrict__ part, float* __restrict__ colred)
{
    const int col   = blockIdx.x * blockDim.x + threadIdx.x;
    const int which = blockIdx.y;
    const float* p = part + (size_t)which * 32 * DIM;
    float s = 0.0f;
    #pragma unroll
    for (int c = 0; c < 32; c++) s += p[c * DIM + col];
    const float scale = which == 2 ? 1.0f : (1.0f / NT);
    colred[which * DIM + col] = s * scale;
}

// ---------------- gate = softmax(m) over tokens ----------------
__global__ __launch_bounds__(1024)
void gate_kernel(const float* __restrict__ m, float* __restrict__ gate)
{
    __shared__ float red[32];
    const int tid = threadIdx.x, lane = tid & 31, wid = tid >> 5;
    float v[8];
    float vmax = -INFINITY;
    #pragma unroll
    for (int k = 0; k < 8; k++) { v[k] = m[tid + k * 1024]; vmax = fmaxf(vmax, v[k]); }
    vmax = warpMax(vmax);
    if (lane == 0) red[wid] = vmax;
    __syncthreads();
    float rmax = red[0];
    #pragma unroll
    for (int c = 1; c < 32; c++) rmax = fmaxf(rmax, red[c]);
    float s = 0.0f;
    #pragma unroll
    for (int k = 0; k < 8; k++) { v[k] = __expf(v[k] - rmax); s += v[k]; }
    s = warpSum(s);
    __syncthreads();
    if (lane == 0) red[wid] = s;
    __syncthreads();
    float tot = 0.0f;
    #pragma unroll
    for (int c = 0; c < 32; c++) tot += red[c];
    const float inv = 1.0f / tot;
    #pragma unroll
    for (int k = 0; k < 8; k++) gate[tid + k * 1024] = v[k] * inv;
}

// ---------------- center + split: qc=(qhat-mq)*c, kc=khat-mk -> bf16 hi/lo ----------------
__global__ __launch_bounds__(256)
void center_split_kernel(const float* __restrict__ qhat, const float* __restrict__ khat,
                         const float* __restrict__ colred, const float* __restrict__ cptr,
                         __nv_bfloat16* __restrict__ qch, __nv_bfloat16* __restrict__ qcl,
                         __nv_bfloat16* __restrict__ kch, __nv_bfloat16* __restrict__ kcl)
{
    const float c = *cptr;
    const size_t i4   = (size_t)blockIdx.x * blockDim.x + threadIdx.x;
    const size_t i    = i4 * 4;
    const int    col4 = (int)(i4 & (DIM / 4 - 1));
    float4 mq = reinterpret_cast<const float4*>(colred)[col4];
    float4 mk = reinterpret_cast<const float4*>(colred + DIM)[col4];
    float4 q = *reinterpret_cast<const float4*>(qhat + i);
    float4 k = *reinterpret_cast<const float4*>(khat + i);
    q.x = (q.x - mq.x) * c; q.y = (q.y - mq.y) * c;
    q.z = (q.z - mq.z) * c; q.w = (q.w - mq.w) * c;
    k.x -= mk.x; k.y -= mk.y; k.z -= mk.z; k.w -= mk.w;
    __nv_bfloat16 h[4], l[4];
    f2split(q.x, h[0], l[0]); f2split(q.y, h[1], l[1]);
    f2split(q.z, h[2], l[2]); f2split(q.w, h[3], l[3]);
    *reinterpret_cast<uint2*>(qch + i) = *reinterpret_cast<uint2*>(h);
    *reinterpret_cast<uint2*>(qcl + i) = *reinterpret_cast<uint2*>(l);
    f2split(k.x, h[0], l[0]); f2split(k.y, h[1], l[1]);
    f2split(k.z, h[2], l[2]); f2split(k.w, h[3], l[3]);
    *reinterpret_cast<uint2*>(kch + i) = *reinterpret_cast<uint2*>(h);
    *reinterpret_cast<uint2*>(kcl + i) = *reinterpret_cast<uint2*>(l);
}

// ---------------- row softmax of S -> bf16 (512 threads/row) ----------------
__global__ __launch_bounds__(512)
void softmax_bf16_kernel(const float* __restrict__ S, __nv_bfloat16* __restrict__ Sh)
{
    __shared__ float buf[NT];
    __shared__ float red[16];
    const int tid = threadIdx.x, lane = tid & 31, wid = tid >> 5;
    const float* Sr = S + (size_t)blockIdx.x * NT;
    __nv_bfloat16* ShR = Sh + (size_t)blockIdx.x * NT;

    float vmax = -INFINITY;
    #pragma unroll
    for (int k = 0; k < 4; k++) {
        int i = (tid + k * 512) * 4;
        float4 v = *reinterpret_cast<const float4*>(Sr + i);
        *reinterpret_cast<float4*>(buf + i) = v;
        vmax = fmaxf(vmax, fmaxf(fmaxf(v.x, v.y), fmaxf(v.z, v.w)));
    }
    vmax = warpMax(vmax);
    if (lane == 0) red[wid] = vmax;
    __syncthreads();
    float rmax = red[0];
    #pragma unroll
    for (int c = 1; c < 16; c++) rmax = fmaxf(rmax, red[c]);

    float ssum = 0.0f;
    #pragma unroll
    for (int k = 0; k < 4; k++) {
        int i = (tid + k * 512) * 4;
        float4 v = *reinterpret_cast<float4*>(buf + i);
        v.x = __expf(v.x - rmax); v.y = __expf(v.y - rmax);
        v.z = __expf(v.z - rmax); v.w = __expf(v.w - rmax);
        ssum += v.x + v.y + v.z + v.w;
        *reinterpret_cast<float4*>(buf + i) = v;
    }
    ssum = warpSum(ssum);
    __syncthreads();
    if (lane == 0) red[wid] = ssum;
    __syncthreads();
    float tot = 0.0f;
    #pragma unroll
    for (int c = 0; c < 16; c++) tot += red[c];
    const float inv = 1.0f / tot;
    #pragma unroll
    for (int k = 0; k < 4; k++) {
        int i = (tid + k * 512) * 4;
        float4 v = *reinterpret_cast<float4*>(buf + i);
        __nv_bfloat16 h[4];
        h[0] = __float2bfloat16_rn(v.x * inv);
        h[1] = __float2bfloat16_rn(v.y * inv);
        h[2] = __float2bfloat16_rn(v.z * inv);
        h[3] = __float2bfloat16_rn(v.w * inv);
        *reinterpret_cast<uint2*>(ShR + i) = *reinterpret_cast<uint2*>(h);
    }
}

// ---------------- host launch ----------------
extern "C" void kernel_launch(void* const* d_in, const int* in_sizes, int n_in,
                              void* d_out, int out_size)
{
    const float* x    = (const float*)d_in[0];
    const float* Wq   = (const float*)d_in[1];
    const float* Wk   = (const float*)d_in[2];
    const float* Wg   = (const float*)d_in[3];
    const float* Wm_w = (const float*)d_in[4];
    const float* Wm_b = (const float*)d_in[5];
    const float* cs   = (const float*)d_in[6];
    float* out = (float*)d_out;

    float *qhat, *khat, *g, *S, *part, *colred, *mv, *gate;
    __nv_bfloat16 *Sh, *xh, *xl, *qch, *qcl, *kch, *kcl, *gTh, *WTh, *WTl;
    cudaGetSymbolAddress((void**)&qhat, d_qhat);
    cudaGetSymbolAddress((void**)&khat, d_khat);
    cudaGetSymbolAddress((void**)&g,    d_g);
    cudaGetSymbolAddress((void**)&S,    d_S);
    cudaGetSymbolAddress((void**)&Sh,   d_Sh);
    cudaGetSymbolAddress((void**)&xh,   d_xh);
    cudaGetSymbolAddress((void**)&xl,   d_xl);
    cudaGetSymbolAddress((void**)&qch,  d_qch);
    cudaGetSymbolAddress((void**)&qcl,  d_qcl);
    cudaGetSymbolAddress((void**)&kch,  d_kch);
    cudaGetSymbolAddress((void**)&kcl,  d_kcl);
    cudaGetSymbolAddress((void**)&gTh,  d_gTh);
    cudaGetSymbolAddress((void**)&WTh,  d_WTh);
    cudaGetSymbolAddress((void**)&WTl,  d_WTl);
    cudaGetSymbolAddress((void**)&part, d_part);
    cudaGetSymbolAddress((void**)&colred, d_colred);
    cudaGetSymbolAddress((void**)&mv,   d_m);
    cudaGetSymbolAddress((void**)&gate, d_gate);

    __nv_bfloat16* WqTh = WTh;
    __nv_bfloat16* WqTl = WTl;
    __nv_bfloat16* WkTh = WTh + (size_t)DIM * DIM;
    __nv_bfloat16* WkTl = WTl + (size_t)DIM * DIM;
    __nv_bfloat16* WgTh = WTh + (size_t)2 * DIM * DIM;
    __nv_bfloat16* WgTl = WTl + (size_t)2 * DIM * DIM;
    float* gsum = colred + 2 * DIM;

    cudaFuncSetAttribute(mmagemm<false, true, 3>,  cudaFuncAttributeMaxDynamicSharedMemorySize, GEMM_SMEM3);
    cudaFuncSetAttribute(mmagemm<false, false, 3>, cudaFuncAttributeMaxDynamicSharedMemorySize, GEMM_SMEM3);
    cudaFuncSetAttribute(mmagemm<true, false, 1>,  cudaFuncAttributeMaxDynamicSharedMemorySize, GEMM_SMEM1);

    const dim3 gW(DIM / 32, DIM / 32);
    const dim3 gGT(DIM / 32, NT / 32);
    const dim3 gProj3(3 * DIM / 128, NT / 128);  // (24, 64) fused q/k/g projections
    const dim3 gOut(DIM / 128, NT / 128);        // (8, 64)
    const dim3 gS(NT / 128, NT / 128);           // (64, 64)

    // 0) prepasses: weights -> transposed bf16 hi/lo ; x -> bf16 hi/lo
    transpose_split_kernel<true><<<gW, 256>>>(Wq, WqTh, WqTl, DIM, DIM);
    transpose_split_kernel<true><<<gW, 256>>>(Wk, WkTh, WkTl, DIM, DIM);
    transpose_split_kernel<true><<<gW, 256>>>(Wg, WgTh, WgTl, DIM, DIM);
    split_kernel<<<(NT * DIM / 4) / 256, 256>>>(x, xh, xl);

    // 1) fused projections: [qhat | khat | g] = x @ [Wq | Wk | Wg]
    mmagemm<false, true, 3><<<gProj3, 512, GEMM_SMEM3>>>(xh, xl, WTh, WTl,
                                                         qhat, khat, g, DIM, DIM,
                                                         nullptr, nullptr, nullptr);

    // 2) gate
    mvec_kernel<<<NT / 8, 256>>>(x, Wm_w, Wm_b, mv);
    gate_kernel<<<1, 1024>>>(mv, gate);

    // 3) merged column reductions (mq, mk, gsum)
    colsum_partial3<<<dim3(DIM / 256, 32, 3), 256>>>(qhat, khat, g, part);
    colsum_final3<<<dim3(DIM / 256, 3), 256>>>(part, colred);

    // 4) center + split to bf16 hi/lo (fold c into q)
    center_split_kernel<<<(NT * (DIM / 4)) / 256, 256>>>(qhat, khat, colred, cs,
                                                         qch, qcl, kch, kcl);

    // 5) transpose g -> gT bf16 (hi only; out-GEMM is single-term)
    transpose_split_kernel<false><<<gGT, 256>>>(g, gTh, nullptr, NT, DIM);

    // 6) S = qc @ kc^T (fp32 out, 3-term for softmax accuracy)
    mmagemm<false, false, 3><<<gS, 512, GEMM_SMEM3>>>(qch, qcl, kch, kcl,
                                                      S, nullptr, nullptr, DIM, NT,
                                                      nullptr, nullptr, nullptr);

    // 7) row softmax -> attn bf16
    softmax_bf16_kernel<<<NT, 512>>>(S, Sh);

    // 8) out = attn @ g + gate[i]*gsum[j] + x   (single-term bf16)
    mmagemm<true, false, 1><<<gOut, 512, GEMM_SMEM1>>>(Sh, nullptr, gTh, nullptr,
                                                       out, nullptr, nullptr, NT, DIM,
                                                       gate, gsum, x);
}